// round 1
// baseline (speedup 1.0000x reference)
#include <cuda_runtime.h>

#define NB 4
#define NH 16
#define SEQ 2048
#define DIM 1024
#define HD 64
#define SCALE 0.03125f   // 1/sqrt(1024)

// Scratch (allocation-free rule: __device__ globals)
__device__ float g_linv[NB * NH * SEQ];                 // 1 / sum_q exp(s[q,k])
__device__ float g_att[(size_t)NB * SEQ * DIM];         // attention output before final linear

// ---------------------------------------------------------------------------
// Swizzled transposed tile: element (d, col), 128 cols per row, LDT = 128.
// XOR swizzle on the 16B-chunk index keeps float4 reads conflict-free and
// cuts transpose-store conflicts to 2-way.
// ---------------------------------------------------------------------------
__device__ __forceinline__ int swz(int d, int col) {
    return d * 128 + (((((col >> 2) ^ ((d >> 2) & 7)) << 2)) | (col & 3));
}

// Load a 128-row x 64-col global panel (row stride ldg) into transposed
// swizzled smem tile Tt[d][row]. Fully coalesced global reads (256B/half-warp).
__device__ __forceinline__ void load_tileT(const float* __restrict__ gp, int ldg,
                                           float* __restrict__ Tt) {
    int tid = threadIdx.x;
    int c  = (tid & 15) << 2;   // d offset: 0..60
    int rb = tid >> 4;          // row base: 0..15
#pragma unroll
    for (int it = 0; it < 8; it++) {
        int r = rb + (it << 4);
        float4 v = *(const float4*)(gp + (size_t)r * ldg + c);
        Tt[swz(c + 0, r)] = v.x;
        Tt[swz(c + 1, r)] = v.y;
        Tt[swz(c + 2, r)] = v.z;
        Tt[swz(c + 3, r)] = v.w;
    }
}

// 128x128 output tile, inner dim 64. Quadrant fragment layout:
// rows R(i) = (i<4 ? ty*4+i : 64+ty*4+i-4), cols C(j) analogous with tx.
__device__ __forceinline__ void gemm_tile_64(const float* __restrict__ At,
                                             const float* __restrict__ Bt,
                                             float acc[8][8], int tx, int ty) {
#pragma unroll 16
    for (int d = 0; d < 64; d++) {
        float4 a0 = *(const float4*)&At[swz(d, ty << 2)];
        float4 a1 = *(const float4*)&At[swz(d, 64 + (ty << 2))];
        float4 b0 = *(const float4*)&Bt[swz(d, tx << 2)];
        float4 b1 = *(const float4*)&Bt[swz(d, 64 + (tx << 2))];
        float a[8]  = {a0.x, a0.y, a0.z, a0.w, a1.x, a1.y, a1.z, a1.w};
        float bb[8] = {b0.x, b0.y, b0.z, b0.w, b1.x, b1.y, b1.z, b1.w};
#pragma unroll
        for (int i = 0; i < 8; i++)
#pragma unroll
            for (int j = 0; j < 8; j++)
                acc[i][j] = fmaf(a[i], bb[j], acc[i][j]);
    }
}

// ---------------------------------------------------------------------------
// Kernel 1: column stats. Rows of the tile = k, cols = q (i.e. S^T tiles).
// l[k] = sum_q exp(s[q,k]) ; store reciprocal. No max needed (|s| <~ 1.5).
// ---------------------------------------------------------------------------
__global__ void __launch_bounds__(256) k1_colsum(const float* __restrict__ Qg,
                                                 const float* __restrict__ Kg) {
    extern __shared__ float sm[];
    float* Kt = sm;               // 64*128
    float* Qt = sm + 64 * 128;    // 64*128
    int b = blockIdx.z, h = blockIdx.y;
    int k0 = blockIdx.x << 7;
    int tid = threadIdx.x;
    int tx = tid & 15, ty = tid >> 4;

    const float* Kbase = Kg + ((size_t)b * SEQ + k0) * DIM + h * HD;
    const float* Qbase = Qg + (size_t)b * SEQ * DIM + h * HD;

    load_tileT(Kbase, DIM, Kt);

    float sume[8];
#pragma unroll
    for (int i = 0; i < 8; i++) sume[i] = 0.f;

    for (int q0 = 0; q0 < SEQ; q0 += 128) {
        __syncthreads();
        load_tileT(Qbase + (size_t)q0 * DIM, DIM, Qt);
        __syncthreads();

        float acc[8][8];
#pragma unroll
        for (int i = 0; i < 8; i++)
#pragma unroll
            for (int j = 0; j < 8; j++) acc[i][j] = 0.f;

        gemm_tile_64(Kt, Qt, acc, tx, ty);   // rows=k (Kt), cols=q (Qt)

#pragma unroll
        for (int i = 0; i < 8; i++) {
            float s = 0.f;
#pragma unroll
            for (int j = 0; j < 8; j++) s += __expf(acc[i][j] * SCALE);
            sume[i] += s;
        }
    }

    // reduce across tx (the 16 threads sharing each k row are a half-warp)
#pragma unroll
    for (int i = 0; i < 8; i++) {
        float v = sume[i];
        v += __shfl_xor_sync(0xffffffffu, v, 1);
        v += __shfl_xor_sync(0xffffffffu, v, 2);
        v += __shfl_xor_sync(0xffffffffu, v, 4);
        v += __shfl_xor_sync(0xffffffffu, v, 8);
        if (tx == 0) {
            int r = (i < 4) ? ((ty << 2) + i) : (64 + (ty << 2) + i - 4);
            g_linv[((size_t)b * NH + h) * SEQ + k0 + r] = 1.0f / v;
        }
    }
}

// ---------------------------------------------------------------------------
// Kernel 2: out[q,:] = sum_k exp(s[q,k])*linv[k] * v[k,:]   per (b,h,qblock).
// gemm1 (S tile) -> P to smem (k-major, swizzled) -> gemm2 (P @ V).
// ---------------------------------------------------------------------------
__global__ void __launch_bounds__(256) k2_attnv(const float* __restrict__ Qg,
                                                const float* __restrict__ Kg,
                                                const float* __restrict__ Vg) {
    extern __shared__ float sm[];
    float* Qt = sm;                    // 64*128   (d-major, q cols)
    float* Kt = Qt + 64 * 128;         // 64*128   (d-major, k cols)
    float* Ps = Kt + 64 * 128;         // 128*128  (k-major rows, q cols, swizzled)
    float* Vs = Ps + 128 * 128;        // 128*64   (k rows, plain)

    int b = blockIdx.z, h = blockIdx.y;
    int q0 = blockIdx.x << 7;
    int tid = threadIdx.x;
    int tx = tid & 15, ty = tid >> 4;

    const float* Qbase = Qg + ((size_t)b * SEQ + q0) * DIM + h * HD;
    const float* Kbase = Kg + (size_t)b * SEQ * DIM + h * HD;
    const float* Vbase = Vg + (size_t)b * SEQ * DIM + h * HD;
    const float* linv = g_linv + ((size_t)b * NH + h) * SEQ;

    load_tileT(Qbase, DIM, Qt);

    float outv[8][4];
#pragma unroll
    for (int i = 0; i < 8; i++)
#pragma unroll
        for (int j = 0; j < 4; j++) outv[i][j] = 0.f;

    int vk = tid >> 4;          // V load: row base
    int vc = (tid & 15) << 2;   // V load: col

    for (int k0 = 0; k0 < SEQ; k0 += 128) {
        __syncthreads();
        load_tileT(Kbase + (size_t)k0 * DIM, DIM, Kt);
#pragma unroll
        for (int it = 0; it < 8; it++) {
            int r = vk + (it << 4);
            *(float4*)&Vs[r * 64 + vc] =
                *(const float4*)(Vbase + (size_t)(k0 + r) * DIM + vc);
        }
        __syncthreads();

        // gemm1: rows = q (Qt), cols = k (Kt)
        float acc[8][8];
#pragma unroll
        for (int i = 0; i < 8; i++)
#pragma unroll
            for (int j = 0; j < 8; j++) acc[i][j] = 0.f;
        gemm_tile_64(Qt, Kt, acc, tx, ty);

        // P = exp(s)*linv[k], stored transposed: Ps[k][q]
#pragma unroll
        for (int j = 0; j < 8; j++) {
            int kk = (j < 4) ? ((tx << 2) + j) : (64 + (tx << 2) + j - 4);
            float rl = linv[k0 + kk];
            float4 p0, p1;
            p0.x = __expf(acc[0][j] * SCALE) * rl;
            p0.y = __expf(acc[1][j] * SCALE) * rl;
            p0.z = __expf(acc[2][j] * SCALE) * rl;
            p0.w = __expf(acc[3][j] * SCALE) * rl;
            p1.x = __expf(acc[4][j] * SCALE) * rl;
            p1.y = __expf(acc[5][j] * SCALE) * rl;
            p1.z = __expf(acc[6][j] * SCALE) * rl;
            p1.w = __expf(acc[7][j] * SCALE) * rl;
            *(float4*)&Ps[swz(kk, ty << 2)] = p0;
            *(float4*)&Ps[swz(kk, 64 + (ty << 2))] = p1;
        }
        __syncthreads();

        // gemm2: out[q][dd] += Ps[k][q] * Vs[k][dd]; dd cols = tx*4..+3
#pragma unroll 8
        for (int k = 0; k < 128; k++) {
            float4 a0 = *(const float4*)&Ps[swz(k, ty << 2)];
            float4 a1 = *(const float4*)&Ps[swz(k, 64 + (ty << 2))];
            float4 vv = *(const float4*)&Vs[k * 64 + (tx << 2)];
            float a[8] = {a0.x, a0.y, a0.z, a0.w, a1.x, a1.y, a1.z, a1.w};
#pragma unroll
            for (int i = 0; i < 8; i++) {
                outv[i][0] = fmaf(a[i], vv.x, outv[i][0]);
                outv[i][1] = fmaf(a[i], vv.y, outv[i][1]);
                outv[i][2] = fmaf(a[i], vv.z, outv[i][2]);
                outv[i][3] = fmaf(a[i], vv.w, outv[i][3]);
            }
        }
    }

    float* obase = g_att + ((size_t)b * SEQ + q0) * DIM + h * HD + (tx << 2);
#pragma unroll
    for (int i = 0; i < 8; i++) {
        int r = (i < 4) ? ((ty << 2) + i) : (64 + (ty << 2) + i - 4);
        *(float4*)(obase + (size_t)r * DIM) =
            make_float4(outv[i][0], outv[i][1], outv[i][2], outv[i][3]);
    }
}

// ---------------------------------------------------------------------------
// Kernel 3: out = g_att @ W^T + b.   C[m,n] = sum_d X[m,d] * W[n,d]
// ---------------------------------------------------------------------------
__global__ void __launch_bounds__(256) k3_linear(const float* __restrict__ Wg,
                                                 const float* __restrict__ bg,
                                                 float* __restrict__ Og) {
    extern __shared__ float sm[];
    float* Xt = sm;               // 64*128
    float* Wt = sm + 64 * 128;    // 64*128
    int n0 = blockIdx.x << 7;
    int m0 = blockIdx.y << 7;
    int tid = threadIdx.x;
    int tx = tid & 15, ty = tid >> 4;

    float acc[8][8];
#pragma unroll
    for (int i = 0; i < 8; i++)
#pragma unroll
        for (int j = 0; j < 8; j++) acc[i][j] = 0.f;

    for (int d0 = 0; d0 < DIM; d0 += 64) {
        __syncthreads();
        load_tileT(g_att + (size_t)m0 * DIM + d0, DIM, Xt);
        load_tileT(Wg + (size_t)n0 * DIM + d0, DIM, Wt);
        __syncthreads();
        gemm_tile_64(Xt, Wt, acc, tx, ty);   // rows=m (Xt), cols=n (Wt)
    }

    float4 bb0 = *(const float4*)(bg + n0 + (tx << 2));
    float4 bb1 = *(const float4*)(bg + n0 + 64 + (tx << 2));
#pragma unroll
    for (int i = 0; i < 8; i++) {
        int r = (i < 4) ? ((ty << 2) + i) : (64 + (ty << 2) + i - 4);
        float* orow = Og + (size_t)(m0 + r) * DIM + n0;
        *(float4*)(orow + (tx << 2)) =
            make_float4(acc[i][0] + bb0.x, acc[i][1] + bb0.y,
                        acc[i][2] + bb0.z, acc[i][3] + bb0.w);
        *(float4*)(orow + 64 + (tx << 2)) =
            make_float4(acc[i][4] + bb1.x, acc[i][5] + bb1.y,
                        acc[i][6] + bb1.z, acc[i][7] + bb1.w);
    }
}

// ---------------------------------------------------------------------------

extern "C" void kernel_launch(void* const* d_in, const int* in_sizes, int n_in,
                              void* d_out, int out_size) {
    const float* Q = (const float*)d_in[0];
    const float* K = (const float*)d_in[1];
    const float* V = (const float*)d_in[2];
    const float* W = (const float*)d_in[3];
    const float* bias = (const float*)d_in[4];
    float* out = (float*)d_out;
    (void)in_sizes; (void)n_in; (void)out_size;

    const int smem1 = 2 * 64 * 128 * 4;                                  // 64 KB
    const int smem2 = (2 * 64 * 128 + 128 * 128 + 128 * 64) * 4;         // 160 KB
    const int smem3 = 2 * 64 * 128 * 4;                                  // 64 KB

    cudaFuncSetAttribute(k1_colsum, cudaFuncAttributeMaxDynamicSharedMemorySize, smem1);
    cudaFuncSetAttribute(k2_attnv,  cudaFuncAttributeMaxDynamicSharedMemorySize, smem2);
    cudaFuncSetAttribute(k3_linear, cudaFuncAttributeMaxDynamicSharedMemorySize, smem3);

    dim3 gAttn(SEQ / 128, NH, NB);          // (16,16,4) = 1024 CTAs
    k1_colsum<<<gAttn, 256, smem1>>>(Q, K);
    k2_attnv<<<gAttn, 256, smem2>>>(Q, K, V);

    dim3 gLin(DIM / 128, (NB * SEQ) / 128); // (8,64) = 512 CTAs
    k3_linear<<<gLin, 256, smem3>>>(W, bias, out);
}

// round 2
// speedup vs baseline: 1.0690x; 1.0690x over previous
#include <cuda_runtime.h>

#define NB 4
#define NH 16
#define SEQ 2048
#define DIM 1024
#define HD 64
#define SCALE 0.03125f   // 1/sqrt(1024)

typedef unsigned long long u64;

// Scratch (allocation-free rule: __device__ globals)
__device__ float g_linv[NB * NH * SEQ];                 // 1 / sum_q exp(s[q,k])
__device__ float g_att[(size_t)NB * SEQ * DIM];         // attention output before final linear

// ---------------------------------------------------------------------------
// Packed fp32x2 helpers (Blackwell sm_103a). ptxas never auto-fuses FFMA2;
// must come from PTX fma.rn.f32x2. One issue slot = 2 FMAs.
// ---------------------------------------------------------------------------
__device__ __forceinline__ void ffma2(u64& d, u64 a, u64 b) {
    asm("fma.rn.f32x2 %0, %1, %2, %0;" : "+l"(d) : "l"(a), "l"(b));
}
__device__ __forceinline__ u64 bcast2(float x) {
    u64 r; asm("mov.b64 %0, {%1, %1};" : "=l"(r) : "f"(x)); return r;
}
__device__ __forceinline__ float2 unpk(u64 v) {
    float2 f; asm("mov.b64 {%0, %1}, %2;" : "=f"(f.x), "=f"(f.y) : "l"(v)); return f;
}

// ---------------------------------------------------------------------------
// Swizzled transposed tile: element (d, col), 128 cols per row.
// ---------------------------------------------------------------------------
__device__ __forceinline__ int swz(int d, int col) {
    return d * 128 + (((((col >> 2) ^ ((d >> 2) & 7)) << 2)) | (col & 3));
}

// Load a 128-row x 64-col global panel (row stride ldg) into transposed
// swizzled smem tile Tt[d][row]. Fully coalesced global reads.
__device__ __forceinline__ void load_tileT(const float* __restrict__ gp, int ldg,
                                           float* __restrict__ Tt) {
    int tid = threadIdx.x;
    int c  = (tid & 15) << 2;   // d offset: 0..60
    int rb = tid >> 4;          // row base: 0..15
#pragma unroll
    for (int it = 0; it < 8; it++) {
        int r = rb + (it << 4);
        float4 v = *(const float4*)(gp + (size_t)r * ldg + c);
        Tt[swz(c + 0, r)] = v.x;
        Tt[swz(c + 1, r)] = v.y;
        Tt[swz(c + 2, r)] = v.z;
        Tt[swz(c + 3, r)] = v.w;
    }
}

// 128x128 output tile, inner dim 64, packed-f32x2 accumulators.
// acc[i][jj]: rows R(i) = quadrant(ty, i); col pairs:
//   jj=0 -> (tx*4+0, tx*4+1), jj=1 -> (tx*4+2, tx*4+3),
//   jj=2 -> (64+tx*4+0, +1),  jj=3 -> (64+tx*4+2, +3)
__device__ __forceinline__ void gemm_tile_64_p(const float* __restrict__ At,
                                               const float* __restrict__ Bt,
                                               u64 acc[8][4], int tx, int ty) {
#pragma unroll 16
    for (int d = 0; d < 64; d++) {
        float4 a0 = *(const float4*)&At[swz(d, ty << 2)];
        float4 a1 = *(const float4*)&At[swz(d, 64 + (ty << 2))];
        ulonglong2 b0 = *(const ulonglong2*)&Bt[swz(d, tx << 2)];
        ulonglong2 b1 = *(const ulonglong2*)&Bt[swz(d, 64 + (tx << 2))];
        float a[8]  = {a0.x, a0.y, a0.z, a0.w, a1.x, a1.y, a1.z, a1.w};
        u64 bp[4]   = {b0.x, b0.y, b1.x, b1.y};
#pragma unroll
        for (int i = 0; i < 8; i++) {
            u64 ab = bcast2(a[i]);
#pragma unroll
            for (int j = 0; j < 4; j++) ffma2(acc[i][j], ab, bp[j]);
        }
    }
}

__device__ __forceinline__ int quad(int t, int i) {
    return (i < 4) ? ((t << 2) + i) : (64 + (t << 2) + i - 4);
}

// ---------------------------------------------------------------------------
// Kernel 1: column stats. Rows = k (Kt as A), cols = q.
// l[k] = sum_q exp(s[q,k]) ; store reciprocal. No max needed (|s| <~ 1.5).
// ---------------------------------------------------------------------------
__global__ void __launch_bounds__(256) k1_colsum(const float* __restrict__ Qg,
                                                 const float* __restrict__ Kg) {
    extern __shared__ float sm[];
    float* Kt = sm;               // 64*128
    float* Qt = sm + 64 * 128;    // 64*128
    int b = blockIdx.z, h = blockIdx.y;
    int k0 = blockIdx.x << 7;
    int tid = threadIdx.x;
    int tx = tid & 15, ty = tid >> 4;

    const float* Kbase = Kg + ((size_t)b * SEQ + k0) * DIM + h * HD;
    const float* Qbase = Qg + (size_t)b * SEQ * DIM + h * HD;

    load_tileT(Kbase, DIM, Kt);

    float sume[8];
#pragma unroll
    for (int i = 0; i < 8; i++) sume[i] = 0.f;

    for (int q0 = 0; q0 < SEQ; q0 += 128) {
        __syncthreads();
        load_tileT(Qbase + (size_t)q0 * DIM, DIM, Qt);
        __syncthreads();

        u64 acc[8][4];
#pragma unroll
        for (int i = 0; i < 8; i++)
#pragma unroll
            for (int j = 0; j < 4; j++) acc[i][j] = 0ull;

        gemm_tile_64_p(Kt, Qt, acc, tx, ty);   // rows=k, cols=q

#pragma unroll
        for (int i = 0; i < 8; i++) {
            float s = 0.f;
#pragma unroll
            for (int j = 0; j < 4; j++) {
                float2 v = unpk(acc[i][j]);
                s += __expf(v.x * SCALE) + __expf(v.y * SCALE);
            }
            sume[i] += s;
        }
    }

    // reduce across tx (16 threads sharing each k row = half-warp)
#pragma unroll
    for (int i = 0; i < 8; i++) {
        float v = sume[i];
        v += __shfl_xor_sync(0xffffffffu, v, 1);
        v += __shfl_xor_sync(0xffffffffu, v, 2);
        v += __shfl_xor_sync(0xffffffffu, v, 4);
        v += __shfl_xor_sync(0xffffffffu, v, 8);
        if (tx == 0) {
            g_linv[((size_t)b * NH + h) * SEQ + k0 + quad(ty, i)] = 1.0f / v;
        }
    }
}

// ---------------------------------------------------------------------------
// Kernel 2: out[q,:] = sum_k exp(s[q,k])*linv[k] * v[k,:]   per (b,h,qblock).
// gemm1 computes S^T tile (rows=k, cols=q packed) -> P to smem (k-major rows,
// q cols, swizzled) -> gemm2 (P @ V).
// ---------------------------------------------------------------------------
__global__ void __launch_bounds__(256) k2_attnv(const float* __restrict__ Qg,
                                                const float* __restrict__ Kg,
                                                const float* __restrict__ Vg) {
    extern __shared__ float sm[];
    float* Qt = sm;                    // 64*128   (d-major, q cols)
    float* Kt = Qt + 64 * 128;         // 64*128   (d-major, k cols)
    float* Ps = Kt + 64 * 128;         // 128*128  (k rows, q cols, swizzled)
    float* Vs = Ps + 128 * 128;        // 128*64   (k rows, plain)

    int b = blockIdx.z, h = blockIdx.y;
    int q0 = blockIdx.x << 7;
    int tid = threadIdx.x;
    int tx = tid & 15, ty = tid >> 4;

    const float* Qbase = Qg + ((size_t)b * SEQ + q0) * DIM + h * HD;
    const float* Kbase = Kg + (size_t)b * SEQ * DIM + h * HD;
    const float* Vbase = Vg + (size_t)b * SEQ * DIM + h * HD;
    const float* linv = g_linv + ((size_t)b * NH + h) * SEQ;

    load_tileT(Qbase, DIM, Qt);

    u64 outv[8][2];
#pragma unroll
    for (int i = 0; i < 8; i++) { outv[i][0] = 0ull; outv[i][1] = 0ull; }

    int vk = tid >> 4;          // V load: row base
    int vc = (tid & 15) << 2;   // V load: col

    for (int k0 = 0; k0 < SEQ; k0 += 128) {
        __syncthreads();
        load_tileT(Kbase + (size_t)k0 * DIM, DIM, Kt);
#pragma unroll
        for (int it = 0; it < 8; it++) {
            int r = vk + (it << 4);
            *(float4*)&Vs[r * 64 + vc] =
                *(const float4*)(Vbase + (size_t)(k0 + r) * DIM + vc);
        }
        __syncthreads();

        // gemm1: rows = k (Kt), cols = q (Qt, packed pairs)
        u64 acc[8][4];
#pragma unroll
        for (int i = 0; i < 8; i++)
#pragma unroll
            for (int j = 0; j < 4; j++) acc[i][j] = 0ull;
        gemm_tile_64_p(Kt, Qt, acc, tx, ty);

        // P[k][q] = exp(s)*linv[k]; packed lanes are adjacent q -> float4 rows
#pragma unroll
        for (int i = 0; i < 8; i++) {
            int kk = quad(ty, i);
            float rl = linv[k0 + kk];
            float2 v0 = unpk(acc[i][0]);
            float2 v1 = unpk(acc[i][1]);
            float2 v2 = unpk(acc[i][2]);
            float2 v3 = unpk(acc[i][3]);
            float4 p0, p1;
            p0.x = __expf(v0.x * SCALE) * rl;
            p0.y = __expf(v0.y * SCALE) * rl;
            p0.z = __expf(v1.x * SCALE) * rl;
            p0.w = __expf(v1.y * SCALE) * rl;
            p1.x = __expf(v2.x * SCALE) * rl;
            p1.y = __expf(v2.y * SCALE) * rl;
            p1.z = __expf(v3.x * SCALE) * rl;
            p1.w = __expf(v3.y * SCALE) * rl;
            *(float4*)&Ps[swz(kk, tx << 2)] = p0;
            *(float4*)&Ps[swz(kk, 64 + (tx << 2))] = p1;
        }
        __syncthreads();

        // gemm2: out[q][dd] += Ps[k][q] * Vs[k][dd]; dd pairs = tx*4 .. +3
#pragma unroll 8
        for (int k = 0; k < 128; k++) {
            float4 a0 = *(const float4*)&Ps[swz(k, ty << 2)];
            float4 a1 = *(const float4*)&Ps[swz(k, 64 + (ty << 2))];
            ulonglong2 vv = *(const ulonglong2*)&Vs[k * 64 + (tx << 2)];
            float a[8] = {a0.x, a0.y, a0.z, a0.w, a1.x, a1.y, a1.z, a1.w};
#pragma unroll
            for (int i = 0; i < 8; i++) {
                u64 ab = bcast2(a[i]);
                ffma2(outv[i][0], ab, vv.x);
                ffma2(outv[i][1], ab, vv.y);
            }
        }
    }

    float* obase = g_att + ((size_t)b * SEQ + q0) * DIM + h * HD + (tx << 2);
#pragma unroll
    for (int i = 0; i < 8; i++) {
        float2 o0 = unpk(outv[i][0]);
        float2 o1 = unpk(outv[i][1]);
        *(float4*)(obase + (size_t)quad(ty, i) * DIM) =
            make_float4(o0.x, o0.y, o1.x, o1.y);
    }
}

// ---------------------------------------------------------------------------
// Kernel 3: out = g_att @ W^T + b.   C[m,n] = sum_d X[m,d] * W[n,d]
// ---------------------------------------------------------------------------
__global__ void __launch_bounds__(256) k3_linear(const float* __restrict__ Wg,
                                                 const float* __restrict__ bg,
                                                 float* __restrict__ Og) {
    extern __shared__ float sm[];
    float* Xt = sm;               // 64*128
    float* Wt = sm + 64 * 128;    // 64*128
    int n0 = blockIdx.x << 7;
    int m0 = blockIdx.y << 7;
    int tid = threadIdx.x;
    int tx = tid & 15, ty = tid >> 4;

    u64 acc[8][4];
#pragma unroll
    for (int i = 0; i < 8; i++)
#pragma unroll
        for (int j = 0; j < 4; j++) acc[i][j] = 0ull;

    for (int d0 = 0; d0 < DIM; d0 += 64) {
        __syncthreads();
        load_tileT(g_att + (size_t)m0 * DIM + d0, DIM, Xt);
        load_tileT(Wg + (size_t)n0 * DIM + d0, DIM, Wt);
        __syncthreads();
        gemm_tile_64_p(Xt, Wt, acc, tx, ty);   // rows=m, cols=n (packed)
    }

    float4 bb0 = *(const float4*)(bg + n0 + (tx << 2));
    float4 bb1 = *(const float4*)(bg + n0 + 64 + (tx << 2));
#pragma unroll
    for (int i = 0; i < 8; i++) {
        float2 c0 = unpk(acc[i][0]);
        float2 c1 = unpk(acc[i][1]);
        float2 c2 = unpk(acc[i][2]);
        float2 c3 = unpk(acc[i][3]);
        float* orow = Og + (size_t)(m0 + quad(ty, i)) * DIM + n0;
        *(float4*)(orow + (tx << 2)) =
            make_float4(c0.x + bb0.x, c0.y + bb0.y, c1.x + bb0.z, c1.y + bb0.w);
        *(float4*)(orow + 64 + (tx << 2)) =
            make_float4(c2.x + bb1.x, c2.y + bb1.y, c3.x + bb1.z, c3.y + bb1.w);
    }
}

// ---------------------------------------------------------------------------

extern "C" void kernel_launch(void* const* d_in, const int* in_sizes, int n_in,
                              void* d_out, int out_size) {
    const float* Q = (const float*)d_in[0];
    const float* K = (const float*)d_in[1];
    const float* V = (const float*)d_in[2];
    const float* W = (const float*)d_in[3];
    const float* bias = (const float*)d_in[4];
    float* out = (float*)d_out;
    (void)in_sizes; (void)n_in; (void)out_size;

    const int smem1 = 2 * 64 * 128 * 4;                                  // 64 KB
    const int smem2 = (2 * 64 * 128 + 128 * 128 + 128 * 64) * 4;         // 160 KB
    const int smem3 = 2 * 64 * 128 * 4;                                  // 64 KB

    cudaFuncSetAttribute(k1_colsum, cudaFuncAttributeMaxDynamicSharedMemorySize, smem1);
    cudaFuncSetAttribute(k2_attnv,  cudaFuncAttributeMaxDynamicSharedMemorySize, smem2);
    cudaFuncSetAttribute(k3_linear, cudaFuncAttributeMaxDynamicSharedMemorySize, smem3);

    dim3 gAttn(SEQ / 128, NH, NB);          // (16,16,4) = 1024 CTAs
    k1_colsum<<<gAttn, 256, smem1>>>(Q, K);
    k2_attnv<<<gAttn, 256, smem2>>>(Q, K, V);

    dim3 gLin(DIM / 128, (NB * SEQ) / 128); // (8,64) = 512 CTAs
    k3_linear<<<gLin, 256, smem3>>>(W, bias, out);
}

// round 4
// speedup vs baseline: 1.4346x; 1.3419x over previous
#include <cuda_runtime.h>

#define NB 4
#define NH 16
#define SEQ 2048
#define DIM 1024
#define HD 64
#define SCALE 0.03125f   // 1/sqrt(1024)

typedef unsigned int u32;

// Scratch (allocation-free rule: __device__ globals)
__device__ float g_linv[NB * NH * SEQ];
__device__ float g_att[(size_t)NB * SEQ * DIM];

// ---------------------------------------------------------------------------
// tf32 helpers (portable PTX, sm_80+; no sm_103a-only features)
// ---------------------------------------------------------------------------
__device__ __forceinline__ u32 f2tf(float x) {
    u32 r; asm("cvt.rna.tf32.f32 %0, %1;" : "=r"(r) : "f"(x)); return r;
}
__device__ __forceinline__ void splitf(float x, u32& hi, u32& lo) {
    hi = f2tf(x);
    lo = f2tf(x - __uint_as_float(hi));
}

// m16n8k8 tf32 mma. acc layout: c0=(r,2c) c1=(r,2c+1) c2=(r+8,2c) c3=(r+8,2c+1)
// A frag: a0=(r,c) a1=(r+8,c) a2=(r,c+4) a3=(r+8,c+4), r=lane>>2, c=lane&3
// B frag: b0=(k=c,n=r) b1=(k=c+4,n=r)
__device__ __forceinline__ void mma8(float c[4], uint4 a, uint2 b) {
    asm volatile(
        "mma.sync.aligned.m16n8k8.row.col.f32.tf32.tf32.f32 "
        "{%0,%1,%2,%3}, {%4,%5,%6,%7}, {%8,%9}, {%0,%1,%2,%3};"
        : "+f"(c[0]), "+f"(c[1]), "+f"(c[2]), "+f"(c[3])
        : "r"(a.x), "r"(a.y), "r"(a.z), "r"(a.w), "r"(b.x), "r"(b.y));
}

// ---------------------------------------------------------------------------
// Fragment-packed smem layouts.
// A-pack: [kstep][mtile][lane] uint4  (slot = ((r>>3)&1) | (((k>>2)&1)<<1))
// B-pack: [kstep][ntile][lane] uint2  (slot = (k>>2)&1)
// ---------------------------------------------------------------------------
template<int MT>
__device__ __forceinline__ uint4 ldAf(const u32* A, int ks, int mt, int lane) {
    return *(const uint4*)(A + ((size_t)((ks * MT + mt) * 32 + lane)) * 4);
}
template<int NT>
__device__ __forceinline__ uint2 ldBf(const u32* B, int ks, int nt, int lane) {
    return *(const uint2*)(B + ((size_t)((ks * NT + nt) * 32 + lane)) * 2);
}

// store float4 of 4 consecutive k at (row r, col c4) into A-pack
template<int MT>
__device__ __forceinline__ void stA4(u32* A, int r, int c4, float4 v) {
    int base = (((c4 >> 3) * MT + (r >> 4)) * 32 + ((r & 7) << 2)) * 4
             + (((r >> 3) & 1) | (((c4 >> 2) & 1) << 1));
    A[base + 0]  = f2tf(v.x);
    A[base + 4]  = f2tf(v.y);
    A[base + 8]  = f2tf(v.z);
    A[base + 12] = f2tf(v.w);
}
// store float4 of 4 consecutive k at (n-row n, col c4) into B-pack ([N][K] src)
template<int NT>
__device__ __forceinline__ void stB4_nk(u32* B, int n, int c4, float4 v) {
    int base = (((c4 >> 3) * NT + (n >> 3)) * 32 + ((n & 7) << 2)) * 2
             + ((c4 >> 2) & 1);
    B[base + 0] = f2tf(v.x);
    B[base + 2] = f2tf(v.y);
    B[base + 4] = f2tf(v.z);
    B[base + 6] = f2tf(v.w);
}

// ---------------------------------------------------------------------------
// Kernel 1: l[k] = sum_q exp(s[q,k]); store 1/l.
// A = K panel (M=128 k-rows), B = Q (N=128 q-cols), K-dim = 64.
// ---------------------------------------------------------------------------
__global__ void __launch_bounds__(256) k1_colsum(const float* __restrict__ Qg,
                                                 const float* __restrict__ Kg) {
    extern __shared__ char smc[];
    u32* Ka = (u32*)smc;                         // 32 KB
    u32* Qb = (u32*)(smc + 32768);               // 32 KB
    float* colsum = (float*)(smc + 65536);       // 512 B
    int tid = threadIdx.x, lane = tid & 31, w = tid >> 5;
    int wm = w >> 2, wn = w & 3;                 // warp grid 2x4, tile 64x32
    int b = blockIdx.z, h = blockIdx.y, k0 = blockIdx.x << 7;

    const float* Kb = Kg + ((size_t)b * SEQ + k0) * DIM + h * HD;
    const float* Qbase = Qg + (size_t)b * SEQ * DIM + h * HD;

    int c4 = (tid & 15) << 2, rb = tid >> 4;
#pragma unroll
    for (int it = 0; it < 8; it++) {
        int r = rb + (it << 4);
        stA4<8>(Ka, r, c4, *(const float4*)(Kb + (size_t)r * DIM + c4));
    }
    if (tid < 128) colsum[tid] = 0.f;

    float sume[4][2];
#pragma unroll
    for (int i = 0; i < 4; i++) { sume[i][0] = 0.f; sume[i][1] = 0.f; }

    for (int q0 = 0; q0 < SEQ; q0 += 128) {
        __syncthreads();
#pragma unroll
        for (int it = 0; it < 8; it++) {
            int n = rb + (it << 4);
            stB4_nk<16>(Qb, n, c4,
                        *(const float4*)(Qbase + (size_t)(q0 + n) * DIM + c4));
        }
        __syncthreads();

        float acc[4][4][4];
#pragma unroll
        for (int i = 0; i < 4; i++)
#pragma unroll
            for (int j = 0; j < 4; j++)
#pragma unroll
                for (int t = 0; t < 4; t++) acc[i][j][t] = 0.f;

#pragma unroll
        for (int ks = 0; ks < 8; ks++) {
            uint4 af[4]; uint2 bf[4];
#pragma unroll
            for (int i = 0; i < 4; i++) af[i] = ldAf<8>(Ka, ks, wm * 4 + i, lane);
#pragma unroll
            for (int j = 0; j < 4; j++) bf[j] = ldBf<16>(Qb, ks, wn * 4 + j, lane);
#pragma unroll
            for (int i = 0; i < 4; i++)
#pragma unroll
                for (int j = 0; j < 4; j++) mma8(acc[i][j], af[i], bf[j]);
        }
#pragma unroll
        for (int i = 0; i < 4; i++)
#pragma unroll
            for (int j = 0; j < 4; j++) {
                sume[i][0] += __expf(acc[i][j][0] * SCALE) + __expf(acc[i][j][1] * SCALE);
                sume[i][1] += __expf(acc[i][j][2] * SCALE) + __expf(acc[i][j][3] * SCALE);
            }
    }

#pragma unroll
    for (int i = 0; i < 4; i++)
#pragma unroll
        for (int hh = 0; hh < 2; hh++) {
            float v = sume[i][hh];
            v += __shfl_xor_sync(0xffffffffu, v, 1);
            v += __shfl_xor_sync(0xffffffffu, v, 2);
            if ((lane & 3) == 0)
                atomicAdd(&colsum[wm * 64 + i * 16 + (lane >> 2) + hh * 8], v);
        }
    __syncthreads();
    if (tid < 128)
        g_linv[((size_t)b * NH + h) * SEQ + k0 + tid] = 1.0f / colsum[tid];
}

// ---------------------------------------------------------------------------
// Kernel 2: out[q,:] = sum_k exp(s[q,k]) * (linv[k]*v[k,:]).
// gemm1: S = Q K^T (A=Q, B=K, 128x128x64). P = rna(exp(S*scale)) -> A-pack.
// gemm2: O += P @ V' (128x64x128), V' split hi/lo. O lives in registers.
// ---------------------------------------------------------------------------
__global__ void __launch_bounds__(256) k2_attnv(const float* __restrict__ Qg,
                                                const float* __restrict__ Kg,
                                                const float* __restrict__ Vg) {
    extern __shared__ char smc[];
    u32* Qa = (u32*)smc;                  // 32 KB A-pack (128q x 64d)
    u32* Kb_ = (u32*)(smc + 32768);       // 32 KB B-pack (128k x 64d)
    u32* Pa = (u32*)(smc + 65536);        // 64 KB A-pack (128q x 128k)
    u32* Vh = (u32*)(smc + 131072);       // 32 KB B-pack (128k x 64d)
    u32* Vl = (u32*)(smc + 163840);       // 32 KB

    int tid = threadIdx.x, lane = tid & 31, w = tid >> 5;
    int wm = w >> 2, wn = w & 3;          // gemm1 warp grid 2x4
    int wm2 = w >> 1, wn2 = w & 1;        // gemm2 warp grid 4x2 (32x32/warp)
    int b = blockIdx.z, h = blockIdx.y, q0 = blockIdx.x << 7;

    const float* Qb = Qg + ((size_t)b * SEQ + q0) * DIM + h * HD;
    const float* Kbase = Kg + (size_t)b * SEQ * DIM + h * HD;
    const float* Vbase = Vg + (size_t)b * SEQ * DIM + h * HD;
    const float* linv = g_linv + ((size_t)b * NH + h) * SEQ;

    int c4 = (tid & 15) << 2, rb = tid >> 4;
#pragma unroll
    for (int it = 0; it < 8; it++) {
        int r = rb + (it << 4);
        stA4<8>(Qa, r, c4, *(const float4*)(Qb + (size_t)r * DIM + c4));
    }

    float o[2][4][4];
#pragma unroll
    for (int i = 0; i < 2; i++)
#pragma unroll
        for (int j = 0; j < 4; j++)
#pragma unroll
            for (int t = 0; t < 4; t++) o[i][j][t] = 0.f;

    for (int k0 = 0; k0 < SEQ; k0 += 128) {
        __syncthreads();
        // K tile -> B-pack ([n=k][d] source)
#pragma unroll
        for (int it = 0; it < 8; it++) {
            int n = rb + (it << 4);
            stB4_nk<16>(Kb_, n, c4,
                        *(const float4*)(Kbase + (size_t)(k0 + n) * DIM + c4));
        }
        // V' tile -> hi/lo B-packs ([k][d] source); fold linv
#pragma unroll
        for (int it = 0; it < 8; it++) {
            int k = rb + (it << 4);
            float rl = __ldg(linv + k0 + k);
            float4 v = *(const float4*)(Vbase + (size_t)(k0 + k) * DIM + c4);
            float vv[4] = {v.x * rl, v.y * rl, v.z * rl, v.w * rl};
            int base = (((k >> 3) * 8 + (c4 >> 3)) * 32 + ((c4 & 7) << 2) + (k & 3)) * 2
                     + ((k >> 2) & 1);
#pragma unroll
            for (int m = 0; m < 4; m++) {
                u32 hi, lo; splitf(vv[m], hi, lo);
                Vh[base + m * 8] = hi;
                Vl[base + m * 8] = lo;
            }
        }
        __syncthreads();

        // gemm1: S
        float acc[4][4][4];
#pragma unroll
        for (int i = 0; i < 4; i++)
#pragma unroll
            for (int j = 0; j < 4; j++)
#pragma unroll
                for (int t = 0; t < 4; t++) acc[i][j][t] = 0.f;
#pragma unroll
        for (int ks = 0; ks < 8; ks++) {
            uint4 af[4]; uint2 bf[4];
#pragma unroll
            for (int i = 0; i < 4; i++) af[i] = ldAf<8>(Qa, ks, wm * 4 + i, lane);
#pragma unroll
            for (int j = 0; j < 4; j++) bf[j] = ldBf<16>(Kb_, ks, wn * 4 + j, lane);
#pragma unroll
            for (int i = 0; i < 4; i++)
#pragma unroll
                for (int j = 0; j < 4; j++) mma8(acc[i][j], af[i], bf[j]);
        }

        // P = rna(exp(s*scale)) scattered into A-pack (Mtiles=8, ksteps=16)
#pragma unroll
        for (int i = 0; i < 4; i++)
#pragma unroll
            for (int j = 0; j < 4; j++) {
                int r = wm * 64 + i * 16 + (lane >> 2);
                int kk = wn * 32 + j * 8 + ((lane & 3) << 1);
#pragma unroll
                for (int t = 0; t < 4; t++) {
                    int rr = r + ((t >> 1) << 3);
                    int kc = kk + (t & 1);
                    int idx = (((kc >> 3) * 8 + (rr >> 4)) * 32
                               + ((rr & 7) << 2) + (kc & 3)) * 4
                            + (((rr >> 3) & 1) | (((kc >> 2) & 1) << 1));
                    Pa[idx] = f2tf(__expf(acc[i][j][t] * SCALE));
                }
            }
        __syncthreads();

        // gemm2: O += P @ Vhi + P @ Vlo   (K = 128 -> 16 ksteps)
#pragma unroll
        for (int ks = 0; ks < 16; ks++) {
            uint4 af2[2]; uint2 bh[4], bl[4];
#pragma unroll
            for (int i = 0; i < 2; i++) af2[i] = ldAf<8>(Pa, ks, wm2 * 2 + i, lane);
#pragma unroll
            for (int j = 0; j < 4; j++) {
                bh[j] = ldBf<8>(Vh, ks, wn2 * 4 + j, lane);
                bl[j] = ldBf<8>(Vl, ks, wn2 * 4 + j, lane);
            }
#pragma unroll
            for (int i = 0; i < 2; i++)
#pragma unroll
                for (int j = 0; j < 4; j++) {
                    mma8(o[i][j], af2[i], bh[j]);
                    mma8(o[i][j], af2[i], bl[j]);
                }
        }
    }

    // write O tile
#pragma unroll
    for (int i = 0; i < 2; i++)
#pragma unroll
        for (int j = 0; j < 4; j++) {
            int r = wm2 * 32 + i * 16 + (lane >> 2);
            int d = wn2 * 32 + j * 8 + ((lane & 3) << 1);
            float* p = &g_att[((size_t)b * SEQ + q0 + r) * DIM + h * HD + d];
            *(float2*)p = make_float2(o[i][j][0], o[i][j][1]);
            *(float2*)(p + (size_t)8 * DIM) = make_float2(o[i][j][2], o[i][j][3]);
        }
}

// ---------------------------------------------------------------------------
// Kernel 3: out = g_att @ W^T + b, 3-pass tf32 split (hi*hi + hi*lo + lo*hi).
// ---------------------------------------------------------------------------
__global__ void __launch_bounds__(256) k3_linear(const float* __restrict__ Wg,
                                                 const float* __restrict__ bg,
                                                 float* __restrict__ Og) {
    extern __shared__ char smc[];
    u32* Xh = (u32*)smc;                   // 32 KB A-pack
    u32* Xl = (u32*)(smc + 32768);
    u32* Wh = (u32*)(smc + 65536);         // 32 KB B-pack
    u32* Wl = (u32*)(smc + 98304);

    int tid = threadIdx.x, lane = tid & 31, w = tid >> 5;
    int wm = w >> 2, wn = w & 3;
    int n0 = blockIdx.x << 7, m0 = blockIdx.y << 7;

    float acc[4][4][4];
#pragma unroll
    for (int i = 0; i < 4; i++)
#pragma unroll
        for (int j = 0; j < 4; j++)
#pragma unroll
            for (int t = 0; t < 4; t++) acc[i][j][t] = 0.f;

    int c4 = (tid & 15) << 2, rb = tid >> 4;
    for (int d0 = 0; d0 < DIM; d0 += 64) {
        __syncthreads();
#pragma unroll
        for (int it = 0; it < 8; it++) {
            int r = rb + (it << 4);
            float4 x = *(const float4*)(g_att + (size_t)(m0 + r) * DIM + d0 + c4);
            float4 ww = *(const float4*)(Wg + (size_t)(n0 + r) * DIM + d0 + c4);
            // X split into A-packs
            {
                int base = (((c4 >> 3) * 8 + (r >> 4)) * 32 + ((r & 7) << 2)) * 4
                         + (((r >> 3) & 1) | (((c4 >> 2) & 1) << 1));
                u32 hi, lo;
                splitf(x.x, hi, lo); Xh[base + 0]  = hi; Xl[base + 0]  = lo;
                splitf(x.y, hi, lo); Xh[base + 4]  = hi; Xl[base + 4]  = lo;
                splitf(x.z, hi, lo); Xh[base + 8]  = hi; Xl[base + 8]  = lo;
                splitf(x.w, hi, lo); Xh[base + 12] = hi; Xl[base + 12] = lo;
            }
            // W split into B-packs
            {
                int base = (((c4 >> 3) * 16 + (r >> 3)) * 32 + ((r & 7) << 2)) * 2
                         + ((c4 >> 2) & 1);
                u32 hi, lo;
                splitf(ww.x, hi, lo); Wh[base + 0] = hi; Wl[base + 0] = lo;
                splitf(ww.y, hi, lo); Wh[base + 2] = hi; Wl[base + 2] = lo;
                splitf(ww.z, hi, lo); Wh[base + 4] = hi; Wl[base + 4] = lo;
                splitf(ww.w, hi, lo); Wh[base + 6] = hi; Wl[base + 6] = lo;
            }
        }
        __syncthreads();

#pragma unroll
        for (int ks = 0; ks < 8; ks++) {
            uint4 ah[4], al[4]; uint2 bh[4], bl[4];
#pragma unroll
            for (int i = 0; i < 4; i++) {
                ah[i] = ldAf<8>(Xh, ks, wm * 4 + i, lane);
                al[i] = ldAf<8>(Xl, ks, wm * 4 + i, lane);
            }
#pragma unroll
            for (int j = 0; j < 4; j++) {
                bh[j] = ldBf<16>(Wh, ks, wn * 4 + j, lane);
                bl[j] = ldBf<16>(Wl, ks, wn * 4 + j, lane);
            }
#pragma unroll
            for (int i = 0; i < 4; i++)
#pragma unroll
                for (int j = 0; j < 4; j++) {
                    mma8(acc[i][j], ah[i], bh[j]);
                    mma8(acc[i][j], ah[i], bl[j]);
                    mma8(acc[i][j], al[i], bh[j]);
                }
        }
    }

#pragma unroll
    for (int i = 0; i < 4; i++)
#pragma unroll
        for (int j = 0; j < 4; j++) {
            int r = wm * 64 + i * 16 + (lane >> 2);
            int n = wn * 32 + j * 8 + ((lane & 3) << 1);
            float2 bb = *(const float2*)(bg + n0 + n);
            float* p = Og + (size_t)(m0 + r) * DIM + n0 + n;
            *(float2*)p = make_float2(acc[i][j][0] + bb.x, acc[i][j][1] + bb.y);
            *(float2*)(p + (size_t)8 * DIM) =
                make_float2(acc[i][j][2] + bb.x, acc[i][j][3] + bb.y);
        }
}

// ---------------------------------------------------------------------------

extern "C" void kernel_launch(void* const* d_in, const int* in_sizes, int n_in,
                              void* d_out, int out_size) {
    const float* Q = (const float*)d_in[0];
    const float* K = (const float*)d_in[1];
    const float* V = (const float*)d_in[2];
    const float* W = (const float*)d_in[3];
    const float* bias = (const float*)d_in[4];
    float* out = (float*)d_out;
    (void)in_sizes; (void)n_in; (void)out_size;

    const int smem1 = 65536 + 512;       // K/Q packs + colsum
    const int smem2 = 196608;            // Q,K,P,Vhi,Vlo packs
    const int smem3 = 131072;            // Xhi,Xlo,Whi,Wlo packs

    cudaFuncSetAttribute(k1_colsum, cudaFuncAttributeMaxDynamicSharedMemorySize, smem1);
    cudaFuncSetAttribute(k2_attnv,  cudaFuncAttributeMaxDynamicSharedMemorySize, smem2);
    cudaFuncSetAttribute(k3_linear, cudaFuncAttributeMaxDynamicSharedMemorySize, smem3);

    dim3 gAttn(SEQ / 128, NH, NB);          // 1024 CTAs
    k1_colsum<<<gAttn, 256, smem1>>>(Q, K);
    k2_attnv<<<gAttn, 256, smem2>>>(Q, K, V);

    dim3 gLin(DIM / 128, (NB * SEQ) / 128); // 512 CTAs
    k3_linear<<<gLin, 256, smem3>>>(W, bias, out);
}

// round 5
// speedup vs baseline: 3.1437x; 2.1913x over previous
#include <cuda_runtime.h>

#define NB 4
#define NH 16
#define SEQ 2048
#define DIM 1024
#define HD 64
#define SCALE 0.03125f   // 1/sqrt(1024)

typedef unsigned int u32;

// Scratch (allocation-free rule: __device__ globals)
__device__ float g_linv[NB * NH * SEQ];
__device__ float g_att[(size_t)NB * SEQ * DIM];

// ---------------------------------------------------------------------------
// Low-level helpers (portable sm_80+ PTX)
// ---------------------------------------------------------------------------
__device__ __forceinline__ u32 f2tf(float x) {
    u32 r; asm("cvt.rna.tf32.f32 %0, %1;" : "=r"(r) : "f"(x)); return r;
}
__device__ __forceinline__ u32 prmt_hi(u32 a, u32 b) {   // {lo16=a.hi16, hi16=b.hi16}
    u32 r; asm("prmt.b32 %0, %1, %2, 0x7632;" : "=r"(r) : "r"(a), "r"(b)); return r;
}
__device__ __forceinline__ u32 bf16x2_rn(float hi, float lo) {
    u32 r; asm("cvt.rn.bf16x2.f32 %0, %1, %2;" : "=r"(r) : "f"(hi), "f"(lo)); return r;
}
__device__ __forceinline__ float truncb(float x) {       // exact bf16 truncation
    return __uint_as_float(__float_as_uint(x) & 0xFFFF0000u);
}

// m16n8k8 tf32 mma
__device__ __forceinline__ void mma8(float c[4], uint4 a, uint2 b) {
    asm volatile(
        "mma.sync.aligned.m16n8k8.row.col.f32.tf32.tf32.f32 "
        "{%0,%1,%2,%3}, {%4,%5,%6,%7}, {%8,%9}, {%0,%1,%2,%3};"
        : "+f"(c[0]), "+f"(c[1]), "+f"(c[2]), "+f"(c[3])
        : "r"(a.x), "r"(a.y), "r"(a.z), "r"(a.w), "r"(b.x), "r"(b.y));
}
// m16n8k16 bf16 mma
__device__ __forceinline__ void mma16(float c[4], uint4 a, uint2 b) {
    asm volatile(
        "mma.sync.aligned.m16n8k16.row.col.f32.bf16.bf16.f32 "
        "{%0,%1,%2,%3}, {%4,%5,%6,%7}, {%8,%9}, {%0,%1,%2,%3};"
        : "+f"(c[0]), "+f"(c[1]), "+f"(c[2]), "+f"(c[3])
        : "r"(a.x), "r"(a.y), "r"(a.z), "r"(a.w), "r"(b.x), "r"(b.y));
}

// ---------------------------------------------------------------------------
// tf32 fragment packs (as round 4; proven)
// A-pack: [ks][mt][lane] uint4; B-pack: [ks][nt][lane] uint2
// ---------------------------------------------------------------------------
template<int MT>
__device__ __forceinline__ uint4 ldAf(const u32* A, int ks, int mt, int lane) {
    return *(const uint4*)(A + ((size_t)((ks * MT + mt) * 32 + lane)) * 4);
}
template<int NT>
__device__ __forceinline__ uint2 ldBf(const u32* B, int ks, int nt, int lane) {
    return *(const uint2*)(B + ((size_t)((ks * NT + nt) * 32 + lane)) * 2);
}
template<int MT>
__device__ __forceinline__ void stA4(u32* A, int r, int c4, float4 v) {
    int base = (((c4 >> 3) * MT + (r >> 4)) * 32 + ((r & 7) << 2)) * 4
             + (((r >> 3) & 1) | (((c4 >> 2) & 1) << 1));
    A[base + 0]  = f2tf(v.x);
    A[base + 4]  = f2tf(v.y);
    A[base + 8]  = f2tf(v.z);
    A[base + 12] = f2tf(v.w);
}
template<int NT>
__device__ __forceinline__ void stB4_nk(u32* B, int n, int c4, float4 v) {
    int base = (((c4 >> 3) * NT + (n >> 3)) * 32 + ((n & 7) << 2)) * 2
             + ((c4 >> 2) & 1);
    B[base + 0] = f2tf(v.x);
    B[base + 2] = f2tf(v.y);
    B[base + 4] = f2tf(v.z);
    B[base + 6] = f2tf(v.w);
}

// ---------------------------------------------------------------------------
// bf16 fragment packs (m16n8k16).  B-pack padded: stride 33 lane-pairs.
// A idx: ((ks*8 + mt)*32 + (r&7)*4 + c)*4 + slot,  slot=((r>>3)&1)|((kk>=8)<<1)
// B idx: ((ks*NT + nt)*33 + (n&7)*4 + c)*2 + (kk>=8)
// ---------------------------------------------------------------------------
__device__ __forceinline__ uint4 ldA16(const u32* A, int ks, int mt, int lane) {
    return *(const uint4*)(A + ((size_t)((ks * 8 + mt) * 32 + lane)) * 4);
}
template<int NT>
__device__ __forceinline__ uint2 ldB16(const u32* B, int ks, int nt, int lane) {
    return *(const uint2*)(B + ((size_t)((ks * NT + nt) * 33 + lane)) * 2);
}
// rn-rounded single-precision bf16 A store of a float4 (4 consecutive k at row r)
__device__ __forceinline__ void stA16_rn(u32* A, int r, int c4, float4 v) {
    int ks = c4 >> 4, kkb = c4 & 15;
    const float* f = &v.x;
#pragma unroll
    for (int p = 0; p < 2; p++) {
        int kk = kkb + 2 * p;
        int c = (kk & 7) >> 1, slot = ((r >> 3) & 1) | ((kk >> 3) << 1);
        int idx = ((ks * 8 + (r >> 4)) * 32 + ((r & 7) << 2) + c) * 4 + slot;
        A[idx] = bf16x2_rn(f[2 * p + 1], f[2 * p]);
    }
}
template<int NT>
__device__ __forceinline__ void stB16_rn(u32* B, int n, int c4, float4 v) {
    int ks = c4 >> 4, kkb = c4 & 15;
    const float* f = &v.x;
#pragma unroll
    for (int p = 0; p < 2; p++) {
        int kk = kkb + 2 * p;
        int c = (kk & 7) >> 1, breg = kk >> 3;
        int idx = ((ks * NT + (n >> 3)) * 33 + ((n & 7) << 2) + c) * 2 + breg;
        B[idx] = bf16x2_rn(f[2 * p + 1], f[2 * p]);
    }
}

// ---------------------------------------------------------------------------
// Kernel 1: l[k] = sum_q exp(s[q,k]); store 1/l.  bf16 single-pass QK^T:
// per-element s error ~4e-4 averages out over the 2048-term column sum.
// A = K panel (M=128 k-rows), B = Q (N=128 q-cols), 4 ksteps of 16.
// ---------------------------------------------------------------------------
__global__ void __launch_bounds__(256) k1_colsum(const float* __restrict__ Qg,
                                                 const float* __restrict__ Kg) {
    extern __shared__ u32 smu[];
    u32* Ka = smu;                       // 4096 u32
    u32* Qb = smu + 4096;                // 4224 u32
    float* colsum = (float*)(smu + 8320);
    int tid = threadIdx.x, lane = tid & 31, w = tid >> 5;
    int wm = w >> 2, wn = w & 3;
    int b = blockIdx.z, h = blockIdx.y, k0 = blockIdx.x << 7;

    const float* Kb = Kg + ((size_t)b * SEQ + k0) * DIM + h * HD;
    const float* Qbase = Qg + (size_t)b * SEQ * DIM + h * HD;

    int rb = tid >> 4, c4 = (tid & 15) << 2;
#pragma unroll
    for (int it = 0; it < 8; it++) {
        int r = rb + (it << 4);
        stA16_rn(Ka, r, c4, *(const float4*)(Kb + (size_t)r * DIM + c4));
    }
    if (tid < 128) colsum[tid] = 0.f;

    float sume[4][2];
#pragma unroll
    for (int i = 0; i < 4; i++) { sume[i][0] = 0.f; sume[i][1] = 0.f; }

    for (int q0 = 0; q0 < SEQ; q0 += 128) {
        __syncthreads();
#pragma unroll
        for (int it = 0; it < 8; it++) {
            int n = rb + (it << 4);
            stB16_rn<16>(Qb, n, c4,
                         *(const float4*)(Qbase + (size_t)(q0 + n) * DIM + c4));
        }
        __syncthreads();

        float acc[4][4][4];
#pragma unroll
        for (int i = 0; i < 4; i++)
#pragma unroll
            for (int j = 0; j < 4; j++)
#pragma unroll
                for (int t = 0; t < 4; t++) acc[i][j][t] = 0.f;

#pragma unroll
        for (int ks = 0; ks < 4; ks++) {
            uint4 af[4]; uint2 bf[4];
#pragma unroll
            for (int i = 0; i < 4; i++) af[i] = ldA16(Ka, ks, wm * 4 + i, lane);
#pragma unroll
            for (int j = 0; j < 4; j++) bf[j] = ldB16<16>(Qb, ks, wn * 4 + j, lane);
#pragma unroll
            for (int i = 0; i < 4; i++)
#pragma unroll
                for (int j = 0; j < 4; j++) mma16(acc[i][j], af[i], bf[j]);
        }
#pragma unroll
        for (int i = 0; i < 4; i++)
#pragma unroll
            for (int j = 0; j < 4; j++) {
                sume[i][0] += __expf(acc[i][j][0] * SCALE) + __expf(acc[i][j][1] * SCALE);
                sume[i][1] += __expf(acc[i][j][2] * SCALE) + __expf(acc[i][j][3] * SCALE);
            }
    }

#pragma unroll
    for (int i = 0; i < 4; i++)
#pragma unroll
        for (int hh = 0; hh < 2; hh++) {
            float v = sume[i][hh];
            v += __shfl_xor_sync(0xffffffffu, v, 1);
            v += __shfl_xor_sync(0xffffffffu, v, 2);
            if ((lane & 3) == 0)
                atomicAdd(&colsum[wm * 64 + i * 16 + (lane >> 2) + hh * 8], v);
        }
    __syncthreads();
    if (tid < 128)
        g_linv[((size_t)b * NH + h) * SEQ + k0 + tid] = 1.0f / colsum[tid];
}

// ---------------------------------------------------------------------------
// Kernel 2: out[q,:] = sum_k exp(s[q,k]) * (linv[k]*v[k,:]).
// Warp tile 16q x 128k (8 warps). gemm1 tf32 (S in regs). P converted in
// registers to bf16 hi/lo A-frags of m16n8k16 — no P smem round-trip.
// gemm2: O += Ph*Vh + Ph*Vl + Pl*Vh (bf16), V' = linv*V split in smem.
// ---------------------------------------------------------------------------
__global__ void __launch_bounds__(256) k2_attnv(const float* __restrict__ Qg,
                                                const float* __restrict__ Kg,
                                                const float* __restrict__ Vg) {
    extern __shared__ u32 smu[];
    u32* Qa = smu;             // tf32 A-pack 128q x 64d : 8192
    u32* Kp = smu + 8192;      // tf32 B-pack 128k x 64d : 8192
    u32* Vh = smu + 16384;     // bf16 B-pack 128k x 64d : 4224 (padded)
    u32* Vl = smu + 20608;     // bf16 B-pack            : 4224

    int tid = threadIdx.x, lane = tid & 31, w = tid >> 5;
    int b = blockIdx.z, h = blockIdx.y, q0 = blockIdx.x << 7;

    const float* Qb = Qg + ((size_t)b * SEQ + q0) * DIM + h * HD;
    const float* Kbase = Kg + (size_t)b * SEQ * DIM + h * HD;
    const float* Vbase = Vg + (size_t)b * SEQ * DIM + h * HD;
    const float* linv = g_linv + ((size_t)b * NH + h) * SEQ;

    int rb = tid >> 4, c4 = (tid & 15) << 2;
#pragma unroll
    for (int it = 0; it < 8; it++) {
        int r = rb + (it << 4);
        stA4<8>(Qa, r, c4, *(const float4*)(Qb + (size_t)r * DIM + c4));
    }

    float o[8][4];
#pragma unroll
    for (int nt = 0; nt < 8; nt++)
#pragma unroll
        for (int t = 0; t < 4; t++) o[nt][t] = 0.f;

    for (int k0 = 0; k0 < SEQ; k0 += 128) {
        __syncthreads();   // previous tile fully consumed
        // K tile -> tf32 B-pack
#pragma unroll
        for (int it = 0; it < 8; it++) {
            int n = rb + (it << 4);
            stB4_nk<16>(Kp, n, c4,
                        *(const float4*)(Kbase + (size_t)(k0 + n) * DIM + c4));
        }
        // V' tile -> bf16 hi/lo B-packs. Lanes l and l^16 hold adjacent k rows;
        // exchange so each lane has the (even,odd) pair, then lane<16 writes Vh,
        // lane>=16 writes Vl.
#pragma unroll
        for (int it = 0; it < 8; it++) {
            int kt = rb + (it << 4);
            float rl = __ldg(linv + k0 + kt);
            float4 v = *(const float4*)(Vbase + (size_t)(k0 + kt) * DIM + c4);
            v.x *= rl; v.y *= rl; v.z *= rl; v.w *= rl;
            float4 oth;
            oth.x = __shfl_xor_sync(0xffffffffu, v.x, 16);
            oth.y = __shfl_xor_sync(0xffffffffu, v.y, 16);
            oth.z = __shfl_xor_sync(0xffffffffu, v.z, 16);
            oth.w = __shfl_xor_sync(0xffffffffu, v.w, 16);
            float4 ve, vo;
            if (lane & 16) { ve = oth; vo = v; } else { ve = v; vo = oth; }
            int ke = kt & ~1;
            int ksv = ke >> 4, kk = ke & 15;
            int c = (kk & 7) >> 1, breg = kk >> 3;
            const float* pe = &ve.x; const float* po = &vo.x;
#pragma unroll
            for (int j = 0; j < 4; j++) {
                int d = c4 + j;
                int idx = ((ksv * 8 + (d >> 3)) * 33 + ((d & 7) << 2) + c) * 2 + breg;
                float a = pe[j], bb = po[j];
                if (!(lane & 16))
                    Vh[idx] = prmt_hi(__float_as_uint(a), __float_as_uint(bb));
                else
                    Vl[idx] = bf16x2_rn(bb - truncb(bb), a - truncb(a));
            }
        }
        __syncthreads();

        // gemm1 (tf32): warp w -> q rows [16w,16w+16), all 128 k-cols
        float acc[16][4];
#pragma unroll
        for (int nt = 0; nt < 16; nt++)
#pragma unroll
            for (int t = 0; t < 4; t++) acc[nt][t] = 0.f;
#pragma unroll
        for (int ks = 0; ks < 8; ks++) {
            uint4 a = ldAf<8>(Qa, ks, w, lane);
#pragma unroll
            for (int nt = 0; nt < 16; nt++) {
                uint2 bf = ldBf<16>(Kp, ks, nt, lane);
                mma8(acc[nt], a, bf);
            }
        }

        // exp -> bf16 hi/lo A-frags in registers; gemm2 immediately
#pragma unroll
        for (int ks2 = 0; ks2 < 8; ks2++) {
            float e0 = __expf(acc[2 * ks2][0] * SCALE);
            float e1 = __expf(acc[2 * ks2][1] * SCALE);
            float e2 = __expf(acc[2 * ks2][2] * SCALE);
            float e3 = __expf(acc[2 * ks2][3] * SCALE);
            float e4 = __expf(acc[2 * ks2 + 1][0] * SCALE);
            float e5 = __expf(acc[2 * ks2 + 1][1] * SCALE);
            float e6 = __expf(acc[2 * ks2 + 1][2] * SCALE);
            float e7 = __expf(acc[2 * ks2 + 1][3] * SCALE);
            uint4 ah, al;
            ah.x = prmt_hi(__float_as_uint(e0), __float_as_uint(e1));
            ah.y = prmt_hi(__float_as_uint(e2), __float_as_uint(e3));
            ah.z = prmt_hi(__float_as_uint(e4), __float_as_uint(e5));
            ah.w = prmt_hi(__float_as_uint(e6), __float_as_uint(e7));
            al.x = bf16x2_rn(e1 - truncb(e1), e0 - truncb(e0));
            al.y = bf16x2_rn(e3 - truncb(e3), e2 - truncb(e2));
            al.z = bf16x2_rn(e5 - truncb(e5), e4 - truncb(e4));
            al.w = bf16x2_rn(e7 - truncb(e7), e6 - truncb(e6));
#pragma unroll
            for (int nt = 0; nt < 8; nt++) {
                uint2 bh = ldB16<8>(Vh, ks2, nt, lane);
                uint2 bl = ldB16<8>(Vl, ks2, nt, lane);
                mma16(o[nt], ah, bh);
                mma16(o[nt], ah, bl);
                mma16(o[nt], al, bh);
            }
        }
    }

    int r = lane >> 2, c2 = (lane & 3) << 1;
    float* obase = g_att + ((size_t)b * SEQ + q0 + 16 * w + r) * DIM + h * HD;
#pragma unroll
    for (int nt = 0; nt < 8; nt++) {
        *(float2*)(obase + nt * 8 + c2) = make_float2(o[nt][0], o[nt][1]);
        *(float2*)(obase + (size_t)8 * DIM + nt * 8 + c2) =
            make_float2(o[nt][2], o[nt][3]);
    }
}

// ---------------------------------------------------------------------------
// Kernel 3: out = g_att @ W^T + b.  bf16 3-pass split (Xh*Wh + Xh*Wl + Xl*Wh).
// 128x128 CTA tile, d-chunks of 64, 2 CTAs/SM.
// ---------------------------------------------------------------------------
__global__ void __launch_bounds__(256, 2) k3_linear(const float* __restrict__ Wg,
                                                    const float* __restrict__ bg,
                                                    float* __restrict__ Og) {
    extern __shared__ u32 smu[];
    u32* Xh = smu;             // 4096
    u32* Xl = smu + 4096;      // 4096
    u32* Wh = smu + 8192;      // 4224
    u32* Wl = smu + 12416;     // 4224

    int tid = threadIdx.x, lane = tid & 31, w = tid >> 5;
    int wm = w >> 2, wn = w & 3;
    int n0 = blockIdx.x << 7, m0 = blockIdx.y << 7;

    float acc[4][4][4];
#pragma unroll
    for (int i = 0; i < 4; i++)
#pragma unroll
        for (int j = 0; j < 4; j++)
#pragma unroll
            for (int t = 0; t < 4; t++) acc[i][j][t] = 0.f;

    int rb = tid >> 4, c4 = (tid & 15) << 2;
    for (int d0 = 0; d0 < DIM; d0 += 64) {
        __syncthreads();
#pragma unroll
        for (int it = 0; it < 8; it++) {
            int r = rb + (it << 4);
            float4 x = *(const float4*)(g_att + (size_t)(m0 + r) * DIM + d0 + c4);
            float4 wv = *(const float4*)(Wg + (size_t)(n0 + r) * DIM + d0 + c4);
            const float* xf = &x.x; const float* wf = &wv.x;
            int ks = c4 >> 4, kkb = c4 & 15;
#pragma unroll
            for (int p = 0; p < 2; p++) {
                int kk = kkb + 2 * p;
                int c = (kk & 7) >> 1;
                // X -> A-pack hi/lo
                {
                    int slot = ((r >> 3) & 1) | ((kk >> 3) << 1);
                    int idx = ((ks * 8 + (r >> 4)) * 32 + ((r & 7) << 2) + c) * 4 + slot;
                    float a = xf[2 * p], bb = xf[2 * p + 1];
                    Xh[idx] = prmt_hi(__float_as_uint(a), __float_as_uint(bb));
                    Xl[idx] = bf16x2_rn(bb - truncb(bb), a - truncb(a));
                }
                // W -> B-pack hi/lo
                {
                    int breg = kk >> 3;
                    int idx = ((ks * 16 + (r >> 3)) * 33 + ((r & 7) << 2) + c) * 2 + breg;
                    float a = wf[2 * p], bb = wf[2 * p + 1];
                    Wh[idx] = prmt_hi(__float_as_uint(a), __float_as_uint(bb));
                    Wl[idx] = bf16x2_rn(bb - truncb(bb), a - truncb(a));
                }
            }
        }
        __syncthreads();

#pragma unroll
        for (int ks = 0; ks < 4; ks++) {
            uint4 ah[4], al[4]; uint2 bh[4], bl[4];
#pragma unroll
            for (int i = 0; i < 4; i++) {
                ah[i] = ldA16(Xh, ks, wm * 4 + i, lane);
                al[i] = ldA16(Xl, ks, wm * 4 + i, lane);
            }
#pragma unroll
            for (int j = 0; j < 4; j++) {
                bh[j] = ldB16<16>(Wh, ks, wn * 4 + j, lane);
                bl[j] = ldB16<16>(Wl, ks, wn * 4 + j, lane);
            }
#pragma unroll
            for (int i = 0; i < 4; i++)
#pragma unroll
                for (int j = 0; j < 4; j++) {
                    mma16(acc[i][j], ah[i], bh[j]);
                    mma16(acc[i][j], ah[i], bl[j]);
                    mma16(acc[i][j], al[i], bh[j]);
                }
        }
    }

#pragma unroll
    for (int i = 0; i < 4; i++)
#pragma unroll
        for (int j = 0; j < 4; j++) {
            int r = wm * 64 + i * 16 + (lane >> 2);
            int n = wn * 32 + j * 8 + ((lane & 3) << 1);
            float2 bb = *(const float2*)(bg + n0 + n);
            float* p = Og + (size_t)(m0 + r) * DIM + n0 + n;
            *(float2*)p = make_float2(acc[i][j][0] + bb.x, acc[i][j][1] + bb.y);
            *(float2*)(p + (size_t)8 * DIM) =
                make_float2(acc[i][j][2] + bb.x, acc[i][j][3] + bb.y);
        }
}

// ---------------------------------------------------------------------------

extern "C" void kernel_launch(void* const* d_in, const int* in_sizes, int n_in,
                              void* d_out, int out_size) {
    const float* Q = (const float*)d_in[0];
    const float* K = (const float*)d_in[1];
    const float* V = (const float*)d_in[2];
    const float* W = (const float*)d_in[3];
    const float* bias = (const float*)d_in[4];
    float* out = (float*)d_out;
    (void)in_sizes; (void)n_in; (void)out_size;

    const int smem1 = (4096 + 4224 + 128) * 4;   // 33792
    const int smem2 = 24832 * 4;                 // 99328
    const int smem3 = 16640 * 4;                 // 66560

    cudaFuncSetAttribute(k1_colsum, cudaFuncAttributeMaxDynamicSharedMemorySize, smem1);
    cudaFuncSetAttribute(k2_attnv,  cudaFuncAttributeMaxDynamicSharedMemorySize, smem2);
    cudaFuncSetAttribute(k3_linear, cudaFuncAttributeMaxDynamicSharedMemorySize, smem3);

    dim3 gAttn(SEQ / 128, NH, NB);          // 1024 CTAs
    k1_colsum<<<gAttn, 256, smem1>>>(Q, K);
    k2_attnv<<<gAttn, 256, smem2>>>(Q, K, V);

    dim3 gLin(DIM / 128, (NB * SEQ) / 128); // 512 CTAs
    k3_linear<<<gLin, 256, smem3>>>(W, bias, out);
}